// round 15
// baseline (speedup 1.0000x reference)
#include <cuda_runtime.h>
#include <cuda_fp16.h>
#include <math.h>
#include <stdint.h>
#include <string.h>

// LoFTR linear attention via ldmatrix + mma.sync, fp16 operands / fp32 accum.
// B=8, L=8192, E=256, H=8, D=32.
// Round 15: k2 -> 128-row tiles, m64n64 warp tiles (4.0 MMA/ldsm, less L1 traffic).

#define Es 256
#define NT1 1024            // k1 tiles (64 rows)
#define NT2 512             // k2 tiles (128 rows)

// ---------------- device scratch ----------------
__device__ __half g_W[4][256][256];                      // [mat][n][k] fp16
__device__ __half g_KVp[NT1][8192];                      // per-k1-tile KV partials (fp16)
__device__ float g_Ksp[NT1][256];                        // per-k1-tile Ksum partials
__device__ float g_Ksum[8 * 256];
__device__ __half g_BD[8][8][32][40];                    // [b][h][e][d(pad 40)] = KV^T fp16

// ---------------- helpers ----------------
__device__ __forceinline__ float fmap(float x) { return x > 0.0f ? x + 1.0f : expf(x); }

__device__ __forceinline__ uint32_t pkh(float a, float b) {
    __half2 v = __floats2half2_rn(a, b);
    uint32_t r; memcpy(&r, &v, 4); return r;
}
__device__ __forceinline__ uint32_t smem_u32(const void* p) {
    uint32_t a;
    asm("{ .reg .u64 t; cvta.to.shared.u64 t, %1; cvt.u32.u64 %0, t; }" : "=r"(a) : "l"(p));
    return a;
}
__device__ __forceinline__ void ldsm4(uint32_t& r0, uint32_t& r1, uint32_t& r2, uint32_t& r3,
                                      uint32_t a) {
    asm volatile("ldmatrix.sync.aligned.m8n8.x4.shared.b16 {%0,%1,%2,%3}, [%4];"
                 : "=r"(r0), "=r"(r1), "=r"(r2), "=r"(r3) : "r"(a));
}
__device__ __forceinline__ void ldsm4t(uint32_t& r0, uint32_t& r1, uint32_t& r2, uint32_t& r3,
                                       uint32_t a) {
    asm volatile("ldmatrix.sync.aligned.m8n8.x4.trans.shared.b16 {%0,%1,%2,%3}, [%4];"
                 : "=r"(r0), "=r"(r1), "=r"(r2), "=r"(r3) : "r"(a));
}
__device__ __forceinline__ void mma16816h(float* d, const uint32_t* a, uint32_t b0, uint32_t b1) {
    asm volatile(
        "mma.sync.aligned.m16n8k16.row.col.f32.f16.f16.f32 "
        "{%0,%1,%2,%3},{%4,%5,%6,%7},{%8,%9},{%0,%1,%2,%3};"
        : "+f"(d[0]), "+f"(d[1]), "+f"(d[2]), "+f"(d[3])
        : "r"(a[0]), "r"(a[1]), "r"(a[2]), "r"(a[3]), "r"(b0), "r"(b1));
}
__device__ __forceinline__ void cp16(uint32_t dst, const void* src) {
    asm volatile("cp.async.ca.shared.global [%0], [%1], 16;" :: "r"(dst), "l"(src));
}

// ---------------- k1 smem layout (bytes) ----------------
#define S1_A    0             // A fp16: 64 x 264 = 33792 (V fp16 aliases here later)
#define S1_B0   33792         // staging buf0: 256 x 40 fp16 = 20480
#define S1_B1   54272         // staging buf1: 20480
#define S1_KF   74752         // Kf fp16: 64 x 264 = 33792
#define S1_BIAS 108544        // bk|bv: 2 x 256 fp32 = 2048
#define K1_SMEM 110592

// ---------------- k2 smem layout (bytes) ----------------
#define J_A  0                // fp16 q/Qf/msg: 128 x 264 = 67584
#define J_B0 67584            // staging buf0: 20480
#define J_B1 88064            // staging buf1: 20480
#define J_BD 108544           // 8 heads x 32 x 40 fp16 = 20480
#define J_Z  129024           // 128 x 8 fp32 = 4096
#define J_KS 133120           // 256 fp32 = 1024
#define J_BQ 134144           // bq: 256 fp32 = 1024
#define K2_SMEM 135168

// A stride 264 fp16; B stride 40 fp16. m64n32 warp tile (k1), single product.
__device__ __forceinline__ void mma_block64s(float acc[4][4][4],
                                             uint32_t aF, int m0, int ka,
                                             uint32_t bF, int n0, int kb, int lane) {
    uint32_t Af[4][4], Bf[2][4];
    int ar = m0 + (lane & 15);
    int ac = ka + ((lane >> 4) << 3);
    uint32_t aoff = (uint32_t)(ar * 264 + ac) * 2;
#pragma unroll
    for (int ma = 0; ma < 4; ++ma)
        ldsm4(Af[ma][0], Af[ma][1], Af[ma][2], Af[ma][3], aF + aoff + ma * 16 * 528);
    int br = n0 + (lane & 7) + ((lane >> 4) << 3);
    int bc = kb + (((lane >> 3) & 1) << 3);
    uint32_t boff = (uint32_t)(br * 40 + bc) * 2;
#pragma unroll
    for (int nb = 0; nb < 2; ++nb)
        ldsm4(Bf[nb][0], Bf[nb][1], Bf[nb][2], Bf[nb][3], bF + boff + nb * 16 * 80);
#pragma unroll
    for (int ma = 0; ma < 4; ++ma)
#pragma unroll
        for (int na = 0; na < 4; ++na)
            mma16816h(acc[ma][na], Af[ma],
                      Bf[na >> 1][(na & 1) * 2], Bf[na >> 1][(na & 1) * 2 + 1]);
}

// m64n64 warp tile (k2 big GEMMs): 32 MMA per 8 ldsm.x4.
__device__ __forceinline__ void mma_block6464(float acc[4][8][4],
                                              uint32_t aF, int m0, int ka,
                                              uint32_t bF, int n0, int kb, int lane) {
    uint32_t Af[4][4], Bf[4][4];
    int ar = m0 + (lane & 15);
    int ac = ka + ((lane >> 4) << 3);
    uint32_t aoff = (uint32_t)(ar * 264 + ac) * 2;
#pragma unroll
    for (int ma = 0; ma < 4; ++ma)
        ldsm4(Af[ma][0], Af[ma][1], Af[ma][2], Af[ma][3], aF + aoff + ma * 16 * 528);
    int br = n0 + (lane & 7) + ((lane >> 4) << 3);
    int bc = kb + (((lane >> 3) & 1) << 3);
    uint32_t boff = (uint32_t)(br * 40 + bc) * 2;
#pragma unroll
    for (int nb = 0; nb < 4; ++nb)
        ldsm4(Bf[nb][0], Bf[nb][1], Bf[nb][2], Bf[nb][3], bF + boff + nb * 16 * 80);
#pragma unroll
    for (int ma = 0; ma < 4; ++ma)
#pragma unroll
        for (int na = 0; na < 8; ++na)
            mma16816h(acc[ma][na], Af[ma],
                      Bf[na >> 1][(na & 1) * 2], Bf[na >> 1][(na & 1) * 2 + 1]);
}

// m128n32 warp tile (k2 msg phase).
__device__ __forceinline__ void mma_block12832(float acc[8][4][4],
                                               uint32_t aF, int ka,
                                               uint32_t bF, int kb, int lane) {
    uint32_t Af[8][4], Bf[2][4];
    int ar = (lane & 15);
    int ac = ka + ((lane >> 4) << 3);
    uint32_t aoff = (uint32_t)(ar * 264 + ac) * 2;
#pragma unroll
    for (int ma = 0; ma < 8; ++ma)
        ldsm4(Af[ma][0], Af[ma][1], Af[ma][2], Af[ma][3], aF + aoff + ma * 16 * 528);
    int br = (lane & 7) + ((lane >> 4) << 3);
    int bc = kb + (((lane >> 3) & 1) << 3);
    uint32_t boff = (uint32_t)(br * 40 + bc) * 2;
#pragma unroll
    for (int nb = 0; nb < 2; ++nb)
        ldsm4(Bf[nb][0], Bf[nb][1], Bf[nb][2], Bf[nb][3], bF + boff + nb * 16 * 80);
#pragma unroll
    for (int ma = 0; ma < 8; ++ma)
#pragma unroll
        for (int na = 0; na < 4; ++na)
            mma16816h(acc[ma][na], Af[ma],
                      Bf[na >> 1][(na & 1) * 2], Bf[na >> 1][(na & 1) * 2 + 1]);
}

// ---------------- prep kernels ----------------
__global__ __launch_bounds__(256) void prep_w_kernel(const float* __restrict__ Wq,
                                                     const float* __restrict__ Wk,
                                                     const float* __restrict__ Wv,
                                                     const float* __restrict__ Wm) {
    int id = blockIdx.x * 256 + threadIdx.x;   // 32768
    int m = id >> 13, rem = id & 8191, n = rem >> 5, g = rem & 31;
    const float* W = (m == 0) ? Wq : (m == 1) ? Wk : (m == 2) ? Wv : Wm;
    float4 a = *(const float4*)(W + (size_t)n * 256 + g * 8);
    float4 c = *(const float4*)(W + (size_t)n * 256 + g * 8 + 4);
    *(uint4*)&g_W[m][n][g * 8] =
        make_uint4(pkh(a.x, a.y), pkh(a.z, a.w), pkh(c.x, c.y), pkh(c.z, c.w));
}

__global__ __launch_bounds__(256) void reduce_bd_kernel() {
    int id = blockIdx.x * 256 + threadIdx.x;   // 65536
    int b = id >> 13, i = id & 8191;
    float s = 0.0f;
#pragma unroll 8
    for (int j = 0; j < 128; ++j) s += __half2float(g_KVp[b * 128 + j][i]);
    int h = i >> 10, d = (i >> 5) & 31, e = i & 31;
    g_BD[b][h][e][d] = __float2half_rn(s);
    if (id < 2048) {
        int bb = id >> 8, c = id & 255;
        float ks = 0.0f;
#pragma unroll 8
        for (int j = 0; j < 128; ++j) ks += g_Ksp[bb * 128 + j][c];
        g_Ksum[bb * 256 + c] = ks;
    }
}

// ---- cp.async weight staging: full n256 chunk (256 rows x 32 cols fp16) ----
__device__ __forceinline__ void stage_W(uint32_t buf, int mat, int kc, int t) {
#pragma unroll
    for (int i = 0; i < 4; ++i) {
        int s = t + i * 256, r = s >> 2, qq = s & 3;
        cp16(buf + r * 80 + qq * 16, (const char*)&g_W[mat][r][kc * 32] + qq * 16);
    }
}

// k1: full 256-deep GEMM pass, m64 (all rows), n0 = warp's 32 cols.
__device__ __forceinline__ void run_gemm1(float acc[4][4][4], uint32_t sb,
                                          uint32_t aF, int t, int lane, int n0, int mat) {
    stage_W(sb + S1_B0, mat, 0, t);
    asm volatile("cp.async.commit_group;" ::: "memory");
    for (int kc = 0; kc < 8; ++kc) {
        uint32_t bFa = sb + ((kc & 1) ? S1_B1 : S1_B0);
        if (kc < 7) {
            stage_W(sb + (((kc + 1) & 1) ? S1_B1 : S1_B0), mat, kc + 1, t);
            asm volatile("cp.async.commit_group;" ::: "memory");
            asm volatile("cp.async.wait_group 1;" ::: "memory");
        } else {
            asm volatile("cp.async.wait_group 0;" ::: "memory");
        }
        __syncthreads();
        mma_block64s(acc, aF, 0, kc * 32,      bFa, n0, 0,  lane);
        mma_block64s(acc, aF, 0, kc * 32 + 16, bFa, n0, 16, lane);
        __syncthreads();
    }
}

// k2: full 256-deep GEMM pass, m64n64 warp tile at (m0, n0).
__device__ __forceinline__ void run_gemm2(float acc[4][8][4], uint32_t sb,
                                          uint32_t aF, int t, int lane,
                                          int m0, int n0, int mat) {
    stage_W(sb + J_B0, mat, 0, t);
    asm volatile("cp.async.commit_group;" ::: "memory");
    for (int kc = 0; kc < 8; ++kc) {
        uint32_t bFa = sb + ((kc & 1) ? J_B1 : J_B0);
        if (kc < 7) {
            stage_W(sb + (((kc + 1) & 1) ? J_B1 : J_B0), mat, kc + 1, t);
            asm volatile("cp.async.commit_group;" ::: "memory");
            asm volatile("cp.async.wait_group 1;" ::: "memory");
        } else {
            asm volatile("cp.async.wait_group 0;" ::: "memory");
        }
        __syncthreads();
        mma_block6464(acc, aF, m0, kc * 32,      bFa, n0, 0,  lane);
        mma_block6464(acc, aF, m0, kc * 32 + 16, bFa, n0, 16, lane);
        __syncthreads();
    }
}

// fp32 input -> fp16 A tile (rows64: 16 iters; rows128: 32 iters), stride 264
template <int ROWS>
__device__ __forceinline__ void build_A(unsigned char* sm, int t, int row0,
                                        const float* __restrict__ X) {
    __syncthreads();
#pragma unroll
    for (int i = 0; i < ROWS / 4; ++i) {
        int idx = t + i * 256;
        int r = idx >> 6, c = (idx & 63) * 4;
        float4 xv = *(const float4*)(X + (size_t)(row0 + r) * Es + c);
        *(uint2*)(sm + (uint32_t)(r * 264 + c) * 2) =
            make_uint2(pkh(xv.x, xv.y), pkh(xv.z, xv.w));
    }
    __syncthreads();
}

// ---------------- K1: K/V projections + KV via MMA (64-row tiles) ----------------
__global__ __launch_bounds__(256, 2)
void k1_kernel(const float* __restrict__ kin, const float* __restrict__ vin,
               const float* __restrict__ bk, const float* __restrict__ bv) {
    extern __shared__ unsigned char sm[];
    const uint32_t sb = smem_u32(sm);
    const int t = threadIdx.x, lane = t & 31, wid = t >> 5;
    const int n0 = wid * 32;
    const int tile = blockIdx.x, row0 = tile * 64;

    float* sB = (float*)(sm + S1_BIAS);
    if (t < 128) {
        const float* src = (t < 64) ? bk : bv;
        ((float4*)sB)[t] = ((const float4*)src)[t & 63];
    }

    const uint32_t aF = sb + S1_A;
    const uint32_t kfb = sb + S1_KF;
    const uint32_t vfb = sb + S1_A;

    // ---- Phase K ----
    build_A<64>(sm, t, row0, kin);
    {
        float acc[4][4][4];
#pragma unroll
        for (int ma = 0; ma < 4; ++ma)
#pragma unroll
            for (int na = 0; na < 4; ++na)
#pragma unroll
                for (int i = 0; i < 4; ++i) acc[ma][na][i] = 0.0f;
        run_gemm1(acc, sb, aF, t, lane, n0, 1);
#pragma unroll
        for (int ma = 0; ma < 4; ++ma) {
            int r1 = ma * 16 + (lane >> 2);
            int r2 = r1 + 8;
#pragma unroll
            for (int na = 0; na < 4; ++na) {
                int cg = n0 + na * 8 + (lane & 3) * 2;
                *(uint32_t*)(sm + S1_KF + (uint32_t)(r1 * 264 + cg) * 2) =
                    pkh(fmap(acc[ma][na][0] + sB[cg]), fmap(acc[ma][na][1] + sB[cg + 1]));
                *(uint32_t*)(sm + S1_KF + (uint32_t)(r2 * 264 + cg) * 2) =
                    pkh(fmap(acc[ma][na][2] + sB[cg]), fmap(acc[ma][na][3] + sB[cg + 1]));
            }
        }
    }

    // ---- Phase V ----
    build_A<64>(sm, t, row0, vin);
    {
        float acc[4][4][4];
#pragma unroll
        for (int ma = 0; ma < 4; ++ma)
#pragma unroll
            for (int na = 0; na < 4; ++na)
#pragma unroll
                for (int i = 0; i < 4; ++i) acc[ma][na][i] = 0.0f;
        run_gemm1(acc, sb, aF, t, lane, n0, 2);
        __syncthreads();
#pragma unroll
        for (int ma = 0; ma < 4; ++ma) {
            int r1 = ma * 16 + (lane >> 2);
            int r2 = r1 + 8;
#pragma unroll
            for (int na = 0; na < 4; ++na) {
                int cg = n0 + na * 8 + (lane & 3) * 2;
                *(uint32_t*)(sm + (uint32_t)(r1 * 264 + cg) * 2) =
                    pkh(acc[ma][na][0] + sB[256 + cg], acc[ma][na][1] + sB[256 + cg + 1]);
                *(uint32_t*)(sm + (uint32_t)(r2 * 264 + cg) * 2) =
                    pkh(acc[ma][na][2] + sB[256 + cg], acc[ma][na][3] + sB[256 + cg + 1]);
            }
        }
    }
    __syncthreads();

    // ---- KV via MMA: warp = head, m32(d) x n32(e) x k64(r) ----
    {
        const int head = wid;
        float acc[2][4][4];
#pragma unroll
        for (int ma = 0; ma < 2; ++ma)
#pragma unroll
            for (int na = 0; na < 4; ++na)
#pragma unroll
                for (int i = 0; i < 4; ++i) acc[ma][na][i] = 0.0f;
        for (int ks = 0; ks < 4; ++ks) {
            const int r0 = ks * 16;
            uint32_t At[2][4], Bt[2][4];
            int arow = r0 + ((lane >> 4) << 3) + (lane & 7);
            int acol = head * 32 + (((lane >> 3) & 1) << 3);
#pragma unroll
            for (int ma = 0; ma < 2; ++ma)
                ldsm4t(At[ma][0], At[ma][1], At[ma][2], At[ma][3],
                       kfb + (uint32_t)(arow * 264 + acol + ma * 16) * 2);
            int brow = r0 + (((lane >> 3) & 1) << 3) + (lane & 7);
            int bcol = head * 32 + ((lane >> 4) << 3);
#pragma unroll
            for (int nb = 0; nb < 2; ++nb)
                ldsm4t(Bt[nb][0], Bt[nb][1], Bt[nb][2], Bt[nb][3],
                       vfb + (uint32_t)(brow * 264 + bcol + nb * 16) * 2);
#pragma unroll
            for (int ma = 0; ma < 2; ++ma)
#pragma unroll
                for (int na = 0; na < 4; ++na)
                    mma16816h(acc[ma][na], At[ma],
                              Bt[na >> 1][(na & 1) * 2], Bt[na >> 1][(na & 1) * 2 + 1]);
        }
#pragma unroll
        for (int ma = 0; ma < 2; ++ma) {
            int d1 = ma * 16 + (lane >> 2), d2 = d1 + 8;
#pragma unroll
            for (int na = 0; na < 4; ++na) {
                int e = na * 8 + (lane & 3) * 2;
                *(uint32_t*)&g_KVp[tile][(head * 32 + d1) * 32 + e] =
                    pkh(acc[ma][na][0], acc[ma][na][1]);
                *(uint32_t*)&g_KVp[tile][(head * 32 + d2) * 32 + e] =
                    pkh(acc[ma][na][2], acc[ma][na][3]);
            }
        }
    }

    // ---- Ksum ----
    {
        float s = 0.0f;
#pragma unroll 8
        for (int r = 0; r < 64; ++r)
            s += __half2float(*(const __half*)(sm + S1_KF + (uint32_t)(r * 264 + t) * 2));
        g_Ksp[tile][t] = s;
    }
}

// ---------------- K2: Q-proj + Z + msg + out-proj (128-row tiles, m64n64) ----------------
__global__ __launch_bounds__(256, 1)
void k2_kernel(const float* __restrict__ q, const float* __restrict__ bq,
               float* __restrict__ out) {
    extern __shared__ unsigned char sm[];
    const uint32_t sb = smem_u32(sm);
    const int t = threadIdx.x, lane = t & 31, wid = t >> 5;
    const int wm = wid & 1, wn = wid >> 1;   // 2 m-halves x 4 n-quarters
    const int tile = blockIdx.x, row0 = tile * 128, b = tile >> 6;

    float* sZ  = (float*)(sm + J_Z);
    float* sKs = (float*)(sm + J_KS);
    float* sBq = (float*)(sm + J_BQ);
    const uint32_t aA = sb + J_A;

    // load BD + Ksum + bq
    {
        const uint4* src = (const uint4*)&g_BD[b][0][0][0];
        uint4* dst = (uint4*)(sm + J_BD);
#pragma unroll
        for (int i = 0; i < 5; ++i) dst[t + i * 256] = src[t + i * 256];
        if (t < 64) ((float4*)sKs)[t] = ((const float4*)(g_Ksum + b * 256))[t];
        else if (t < 128) ((float4*)sBq)[t - 64] = ((const float4*)bq)[t - 64];
    }

    // ---- Phase Qf: A = q tile; GEMM x Wq; fmap epilogue in place ----
    build_A<128>(sm, t, row0, q);
    {
        float acc[4][8][4];
#pragma unroll
        for (int ma = 0; ma < 4; ++ma)
#pragma unroll
            for (int na = 0; na < 8; ++na)
#pragma unroll
                for (int i = 0; i < 4; ++i) acc[ma][na][i] = 0.0f;
        run_gemm2(acc, sb, aA, t, lane, wm * 64, wn * 64, 0);
        // trailing sync in run_gemm2 guarantees all MMAs done; safe to overwrite A
#pragma unroll
        for (int ma = 0; ma < 4; ++ma) {
            int r1 = wm * 64 + ma * 16 + (lane >> 2);
            int r2 = r1 + 8;
#pragma unroll
            for (int na = 0; na < 8; ++na) {
                int cg = wn * 64 + na * 8 + (lane & 3) * 2;
                *(uint32_t*)(sm + J_A + (uint32_t)(r1 * 264 + cg) * 2) =
                    pkh(fmap(acc[ma][na][0] + sBq[cg]), fmap(acc[ma][na][1] + sBq[cg + 1]));
                *(uint32_t*)(sm + J_A + (uint32_t)(r2 * 264 + cg) * 2) =
                    pkh(fmap(acc[ma][na][2] + sBq[cg]), fmap(acc[ma][na][3] + sBq[cg + 1]));
            }
        }
    }
    __syncthreads();

    // Z = 1/(Qf . Ksum + eps)   (128 rows x 8 heads = 1024 tasks)
#pragma unroll
    for (int i = 0; i < 4; ++i) {
        int task = t + i * 256;
        int r = task >> 3, h = task & 7;
        float dot = 0.0f;
#pragma unroll
        for (int dp = 0; dp < 16; ++dp) {
            int c = h * 32 + dp * 2;
            uint32_t w = *(const uint32_t*)(sm + J_A + (uint32_t)(r * 264 + c) * 2);
            __half2 hv; memcpy(&hv, &w, 4);
            dot += __half2float(hv.x) * sKs[c] + __half2float(hv.y) * sKs[c + 1];
        }
        sZ[r * 8 + h] = 1.0f / (dot + 1e-6f);
    }
    __syncthreads();

    // msg: warp = head, m128 x n32(e) x k32(d); scale by Z, overwrite A
    {
        const int head = wid;
        float acc[8][4][4];
#pragma unroll
        for (int ma = 0; ma < 8; ++ma)
#pragma unroll
            for (int na = 0; na < 4; ++na)
#pragma unroll
                for (int i = 0; i < 4; ++i) acc[ma][na][i] = 0.0f;
        uint32_t bdF = sb + J_BD + head * 2560;
        mma_block12832(acc, aA + (uint32_t)(head * 32) * 2 - 0, 0, bdF, 0, lane);
        // note: ka passed via pointer column offset would break stride math; use ka arg:
        // (recompute properly below)
#pragma unroll
        for (int ma = 0; ma < 8; ++ma)
#pragma unroll
            for (int na = 0; na < 4; ++na)
#pragma unroll
                for (int i = 0; i < 4; ++i) acc[ma][na][i] = 0.0f;
        mma_block12832(acc, aA, head * 32,      bdF, 0,  lane);
        mma_block12832(acc, aA, head * 32 + 16, bdF, 16, lane);
        __syncthreads();   // all warps done reading A before overwriting
#pragma unroll
        for (int ma = 0; ma < 8; ++ma) {
            int r1 = ma * 16 + (lane >> 2);
            int r2 = r1 + 8;
            float z1 = sZ[r1 * 8 + head], z2 = sZ[r2 * 8 + head];
#pragma unroll
            for (int na = 0; na < 4; ++na) {
                int cg = head * 32 + na * 8 + (lane & 3) * 2;
                *(uint32_t*)(sm + J_A + (uint32_t)(r1 * 264 + cg) * 2) =
                    pkh(acc[ma][na][0] * z1, acc[ma][na][1] * z1);
                *(uint32_t*)(sm + J_A + (uint32_t)(r2 * 264 + cg) * 2) =
                    pkh(acc[ma][na][2] * z2, acc[ma][na][3] * z2);
            }
        }
    }
    __syncthreads();

    // out = msg @ Wm^T: m64n64 warp tiles, cp.async pipelined
    {
        float acc[4][8][4];
#pragma unroll
        for (int ma = 0; ma < 4; ++ma)
#pragma unroll
            for (int na = 0; na < 8; ++na)
#pragma unroll
                for (int i = 0; i < 4; ++i) acc[ma][na][i] = 0.0f;
        run_gemm2(acc, sb, aA, t, lane, wm * 64, wn * 64, 3);
#pragma unroll
        for (int ma = 0; ma < 4; ++ma) {
            int r1 = wm * 64 + ma * 16 + (lane >> 2);
            int r2 = r1 + 8;
#pragma unroll
            for (int na = 0; na < 8; ++na) {
                int cg = wn * 64 + na * 8 + (lane & 3) * 2;
                *(float2*)(out + (size_t)(row0 + r1) * 256 + cg) =
                    make_float2(acc[ma][na][0], acc[ma][na][1]);
                *(float2*)(out + (size_t)(row0 + r2) * 256 + cg) =
                    make_float2(acc[ma][na][2], acc[ma][na][3]);
            }
        }
    }
}

// ---------------------------------------------------------------------------
extern "C" void kernel_launch(void* const* d_in, const int* in_sizes, int n_in,
                              void* d_out, int out_size) {
    const float* q  = (const float*)d_in[0];
    const float* k  = (const float*)d_in[1];
    const float* v  = (const float*)d_in[2];
    const float* Wq = (const float*)d_in[3];
    const float* bq = (const float*)d_in[4];
    const float* Wk = (const float*)d_in[5];
    const float* bk = (const float*)d_in[6];
    const float* Wv = (const float*)d_in[7];
    const float* bv = (const float*)d_in[8];
    const float* Wm = (const float*)d_in[9];
    float* out = (float*)d_out;

    cudaFuncSetAttribute(k1_kernel, cudaFuncAttributeMaxDynamicSharedMemorySize, K1_SMEM);
    cudaFuncSetAttribute(k2_kernel, cudaFuncAttributeMaxDynamicSharedMemorySize, K2_SMEM);

    prep_w_kernel<<<128, 256>>>(Wq, Wk, Wv, Wm);
    k1_kernel<<<NT1, 256, K1_SMEM>>>(k, v, bk, bv);
    reduce_bd_kernel<<<256, 256>>>();
    k2_kernel<<<NT2, 256, K2_SMEM>>>(q, bq, out);
}

// round 16
// speedup vs baseline: 1.0064x; 1.0064x over previous
#include <cuda_runtime.h>
#include <cuda_fp16.h>
#include <math.h>
#include <stdint.h>
#include <string.h>

// LoFTR linear attention via ldmatrix + mma.sync, fp16 operands / fp32 accum.
// B=8, L=8192, E=256, H=8, D=32.
// Round 16: k1 = round-14 (64-row, 2 CTA/SM). k2 = 128-row tiles, 2x4 warp grid,
//           nh-halved staging (round-12 shape) with Q-proj folded in.

#define Es 256
#define NT1 1024            // k1 tiles (64 rows)
#define NT2 512             // k2 tiles (128 rows)

// ---------------- device scratch ----------------
__device__ __half g_W[4][256][256];                      // [mat][n][k] fp16
__device__ __half g_KVp[NT1][8192];                      // per-k1-tile KV partials (fp16)
__device__ float g_Ksp[NT1][256];                        // per-k1-tile Ksum partials
__device__ float g_Ksum[8 * 256];
__device__ __half g_BD[8][8][32][40];                    // [b][h][e][d(pad 40)] = KV^T fp16

// ---------------- helpers ----------------
__device__ __forceinline__ float fmap(float x) { return x > 0.0f ? x + 1.0f : expf(x); }

__device__ __forceinline__ uint32_t pkh(float a, float b) {
    __half2 v = __floats2half2_rn(a, b);
    uint32_t r; memcpy(&r, &v, 4); return r;
}
__device__ __forceinline__ uint32_t smem_u32(const void* p) {
    uint32_t a;
    asm("{ .reg .u64 t; cvta.to.shared.u64 t, %1; cvt.u32.u64 %0, t; }" : "=r"(a) : "l"(p));
    return a;
}
__device__ __forceinline__ void ldsm4(uint32_t& r0, uint32_t& r1, uint32_t& r2, uint32_t& r3,
                                      uint32_t a) {
    asm volatile("ldmatrix.sync.aligned.m8n8.x4.shared.b16 {%0,%1,%2,%3}, [%4];"
                 : "=r"(r0), "=r"(r1), "=r"(r2), "=r"(r3) : "r"(a));
}
__device__ __forceinline__ void ldsm4t(uint32_t& r0, uint32_t& r1, uint32_t& r2, uint32_t& r3,
                                       uint32_t a) {
    asm volatile("ldmatrix.sync.aligned.m8n8.x4.trans.shared.b16 {%0,%1,%2,%3}, [%4];"
                 : "=r"(r0), "=r"(r1), "=r"(r2), "=r"(r3) : "r"(a));
}
__device__ __forceinline__ void mma16816h(float* d, const uint32_t* a, uint32_t b0, uint32_t b1) {
    asm volatile(
        "mma.sync.aligned.m16n8k16.row.col.f32.f16.f16.f32 "
        "{%0,%1,%2,%3},{%4,%5,%6,%7},{%8,%9},{%0,%1,%2,%3};"
        : "+f"(d[0]), "+f"(d[1]), "+f"(d[2]), "+f"(d[3])
        : "r"(a[0]), "r"(a[1]), "r"(a[2]), "r"(a[3]), "r"(b0), "r"(b1));
}
__device__ __forceinline__ void cp16(uint32_t dst, const void* src) {
    asm volatile("cp.async.ca.shared.global [%0], [%1], 16;" :: "r"(dst), "l"(src));
}

// ---------------- k1 smem layout (bytes) ----------------
#define S1_A    0             // A fp16: 64 x 264 = 33792 (V fp16 aliases here later)
#define S1_B0   33792         // staging buf0: 256 x 40 fp16 = 20480
#define S1_B1   54272         // staging buf1: 20480
#define S1_KF   74752         // Kf fp16: 64 x 264 = 33792
#define S1_BIAS 108544        // bk|bv: 2 x 256 fp32 = 2048
#define K1_SMEM 110592

// ---------------- k2 smem layout (bytes) ----------------
#define J_A  0                // fp16 q/Qf/msg: 128 x 264 = 67584
#define J_B0 67584            // staging buf0: 128 x 40 fp16 = 10240
#define J_B1 77824            // staging buf1: 10240
#define J_BD 88064            // 8 heads x 32 x 40 fp16 = 20480
#define J_Z  108544           // 128 x 8 fp32 = 4096
#define J_KS 112640           // 256 fp32 = 1024
#define J_BQ 113664           // bq: 256 fp32 = 1024
#define K2_SMEM 114688

// A stride 264 fp16; B stride 40 fp16. m64n32 warp tile, single product.
__device__ __forceinline__ void mma_block64s(float acc[4][4][4],
                                             uint32_t aF, int m0, int ka,
                                             uint32_t bF, int n0, int kb, int lane) {
    uint32_t Af[4][4], Bf[2][4];
    int ar = m0 + (lane & 15);
    int ac = ka + ((lane >> 4) << 3);
    uint32_t aoff = (uint32_t)(ar * 264 + ac) * 2;
#pragma unroll
    for (int ma = 0; ma < 4; ++ma)
        ldsm4(Af[ma][0], Af[ma][1], Af[ma][2], Af[ma][3], aF + aoff + ma * 16 * 528);
    int br = n0 + (lane & 7) + ((lane >> 4) << 3);
    int bc = kb + (((lane >> 3) & 1) << 3);
    uint32_t boff = (uint32_t)(br * 40 + bc) * 2;
#pragma unroll
    for (int nb = 0; nb < 2; ++nb)
        ldsm4(Bf[nb][0], Bf[nb][1], Bf[nb][2], Bf[nb][3], bF + boff + nb * 16 * 80);
#pragma unroll
    for (int ma = 0; ma < 4; ++ma)
#pragma unroll
        for (int na = 0; na < 4; ++na)
            mma16816h(acc[ma][na], Af[ma],
                      Bf[na >> 1][(na & 1) * 2], Bf[na >> 1][(na & 1) * 2 + 1]);
}

// ---------------- prep kernels ----------------
__global__ __launch_bounds__(256) void prep_w_kernel(const float* __restrict__ Wq,
                                                     const float* __restrict__ Wk,
                                                     const float* __restrict__ Wv,
                                                     const float* __restrict__ Wm) {
    int id = blockIdx.x * 256 + threadIdx.x;   // 32768
    int m = id >> 13, rem = id & 8191, n = rem >> 5, g = rem & 31;
    const float* W = (m == 0) ? Wq : (m == 1) ? Wk : (m == 2) ? Wv : Wm;
    float4 a = *(const float4*)(W + (size_t)n * 256 + g * 8);
    float4 c = *(const float4*)(W + (size_t)n * 256 + g * 8 + 4);
    *(uint4*)&g_W[m][n][g * 8] =
        make_uint4(pkh(a.x, a.y), pkh(a.z, a.w), pkh(c.x, c.y), pkh(c.z, c.w));
}

__global__ __launch_bounds__(256) void reduce_bd_kernel() {
    int id = blockIdx.x * 256 + threadIdx.x;   // 65536
    int b = id >> 13, i = id & 8191;
    float s = 0.0f;
#pragma unroll 8
    for (int j = 0; j < 128; ++j) s += __half2float(g_KVp[b * 128 + j][i]);
    int h = i >> 10, d = (i >> 5) & 31, e = i & 31;
    g_BD[b][h][e][d] = __float2half_rn(s);
    if (id < 2048) {
        int bb = id >> 8, c = id & 255;
        float ks = 0.0f;
#pragma unroll 8
        for (int j = 0; j < 128; ++j) ks += g_Ksp[bb * 128 + j][c];
        g_Ksum[bb * 256 + c] = ks;
    }
}

// ---- k1 staging: full n256 chunk (256 rows x 32 cols fp16) ----
__device__ __forceinline__ void stage_W(uint32_t buf, int mat, int kc, int t) {
#pragma unroll
    for (int i = 0; i < 4; ++i) {
        int s = t + i * 256, r = s >> 2, qq = s & 3;
        cp16(buf + r * 80 + qq * 16, (const char*)&g_W[mat][r][kc * 32] + qq * 16);
    }
}
// ---- k2 staging: half-matrix chunk (128 rows x 32 cols fp16) ----
__device__ __forceinline__ void stage_Wh(uint32_t buf, int mat, int nh, int kc, int t) {
#pragma unroll
    for (int i = 0; i < 2; ++i) {
        int s = t + i * 256, r = s >> 2, qq = s & 3;
        cp16(buf + r * 80 + qq * 16, (const char*)&g_W[mat][nh * 128 + r][kc * 32] + qq * 16);
    }
}

// k1: full 256-deep GEMM, m64 all rows, n0 = warp's 32 cols.
__device__ __forceinline__ void run_gemm1(float acc[4][4][4], uint32_t sb,
                                          uint32_t aF, int t, int lane, int n0, int mat) {
    stage_W(sb + S1_B0, mat, 0, t);
    asm volatile("cp.async.commit_group;" ::: "memory");
    for (int kc = 0; kc < 8; ++kc) {
        uint32_t bFa = sb + ((kc & 1) ? S1_B1 : S1_B0);
        if (kc < 7) {
            stage_W(sb + (((kc + 1) & 1) ? S1_B1 : S1_B0), mat, kc + 1, t);
            asm volatile("cp.async.commit_group;" ::: "memory");
            asm volatile("cp.async.wait_group 1;" ::: "memory");
        } else {
            asm volatile("cp.async.wait_group 0;" ::: "memory");
        }
        __syncthreads();
        mma_block64s(acc, aF, 0, kc * 32,      bFa, n0, 0,  lane);
        mma_block64s(acc, aF, 0, kc * 32 + 16, bFa, n0, 16, lane);
        __syncthreads();
    }
}

// k2: 256-deep GEMM vs weight n-half `nh`, warp tile (m0, n0).
__device__ __forceinline__ void run_gemm2h(float acc[4][4][4], uint32_t sb,
                                           uint32_t aF, int t, int lane,
                                           int m0, int n0, int mat, int nh) {
    stage_Wh(sb + J_B0, mat, nh, 0, t);
    asm volatile("cp.async.commit_group;" ::: "memory");
    for (int kc = 0; kc < 8; ++kc) {
        uint32_t bFa = sb + ((kc & 1) ? J_B1 : J_B0);
        if (kc < 7) {
            stage_Wh(sb + (((kc + 1) & 1) ? J_B1 : J_B0), mat, nh, kc + 1, t);
            asm volatile("cp.async.commit_group;" ::: "memory");
            asm volatile("cp.async.wait_group 1;" ::: "memory");
        } else {
            asm volatile("cp.async.wait_group 0;" ::: "memory");
        }
        __syncthreads();
        mma_block64s(acc, aF, m0, kc * 32,      bFa, n0, 0,  lane);
        mma_block64s(acc, aF, m0, kc * 32 + 16, bFa, n0, 16, lane);
        __syncthreads();
    }
}

// fp32 input -> fp16 A tile, stride 264
template <int ROWS>
__device__ __forceinline__ void build_A(unsigned char* sm, int t, int row0,
                                        const float* __restrict__ X) {
    __syncthreads();
#pragma unroll
    for (int i = 0; i < ROWS / 4; ++i) {
        int idx = t + i * 256;
        int r = idx >> 6, c = (idx & 63) * 4;
        float4 xv = *(const float4*)(X + (size_t)(row0 + r) * Es + c);
        *(uint2*)(sm + (uint32_t)(r * 264 + c) * 2) =
            make_uint2(pkh(xv.x, xv.y), pkh(xv.z, xv.w));
    }
    __syncthreads();
}

// ---------------- K1: K/V projections + KV via MMA (64-row tiles) ----------------
__global__ __launch_bounds__(256, 2)
void k1_kernel(const float* __restrict__ kin, const float* __restrict__ vin,
               const float* __restrict__ bk, const float* __restrict__ bv) {
    extern __shared__ unsigned char sm[];
    const uint32_t sb = smem_u32(sm);
    const int t = threadIdx.x, lane = t & 31, wid = t >> 5;
    const int n0 = wid * 32;
    const int tile = blockIdx.x, row0 = tile * 64;

    float* sB = (float*)(sm + S1_BIAS);
    if (t < 128) {
        const float* src = (t < 64) ? bk : bv;
        ((float4*)sB)[t] = ((const float4*)src)[t & 63];
    }

    const uint32_t aF = sb + S1_A;
    const uint32_t kfb = sb + S1_KF;
    const uint32_t vfb = sb + S1_A;

    // ---- Phase K ----
    build_A<64>(sm, t, row0, kin);
    {
        float acc[4][4][4];
#pragma unroll
        for (int ma = 0; ma < 4; ++ma)
#pragma unroll
            for (int na = 0; na < 4; ++na)
#pragma unroll
                for (int i = 0; i < 4; ++i) acc[ma][na][i] = 0.0f;
        run_gemm1(acc, sb, aF, t, lane, n0, 1);
#pragma unroll
        for (int ma = 0; ma < 4; ++ma) {
            int r1 = ma * 16 + (lane >> 2);
            int r2 = r1 + 8;
#pragma unroll
            for (int na = 0; na < 4; ++na) {
                int cg = n0 + na * 8 + (lane & 3) * 2;
                *(uint32_t*)(sm + S1_KF + (uint32_t)(r1 * 264 + cg) * 2) =
                    pkh(fmap(acc[ma][na][0] + sB[cg]), fmap(acc[ma][na][1] + sB[cg + 1]));
                *(uint32_t*)(sm + S1_KF + (uint32_t)(r2 * 264 + cg) * 2) =
                    pkh(fmap(acc[ma][na][2] + sB[cg]), fmap(acc[ma][na][3] + sB[cg + 1]));
            }
        }
    }

    // ---- Phase V ----
    build_A<64>(sm, t, row0, vin);
    {
        float acc[4][4][4];
#pragma unroll
        for (int ma = 0; ma < 4; ++ma)
#pragma unroll
            for (int na = 0; na < 4; ++na)
#pragma unroll
                for (int i = 0; i < 4; ++i) acc[ma][na][i] = 0.0f;
        run_gemm1(acc, sb, aF, t, lane, n0, 2);
        __syncthreads();
#pragma unroll
        for (int ma = 0; ma < 4; ++ma) {
            int r1 = ma * 16 + (lane >> 2);
            int r2 = r1 + 8;
#pragma unroll
            for (int na = 0; na < 4; ++na) {
                int cg = n0 + na * 8 + (lane & 3) * 2;
                *(uint32_t*)(sm + (uint32_t)(r1 * 264 + cg) * 2) =
                    pkh(acc[ma][na][0] + sB[256 + cg], acc[ma][na][1] + sB[256 + cg + 1]);
                *(uint32_t*)(sm + (uint32_t)(r2 * 264 + cg) * 2) =
                    pkh(acc[ma][na][2] + sB[256 + cg], acc[ma][na][3] + sB[256 + cg + 1]);
            }
        }
    }
    __syncthreads();

    // ---- KV via MMA: warp = head, m32(d) x n32(e) x k64(r) ----
    {
        const int head = wid;
        float acc[2][4][4];
#pragma unroll
        for (int ma = 0; ma < 2; ++ma)
#pragma unroll
            for (int na = 0; na < 4; ++na)
#pragma unroll
                for (int i = 0; i < 4; ++i) acc[ma][na][i] = 0.0f;
        for (int ks = 0; ks < 4; ++ks) {
            const int r0 = ks * 16;
            uint32_t At[2][4], Bt[2][4];
            int arow = r0 + ((lane >> 4) << 3) + (lane & 7);
            int acol = head * 32 + (((lane >> 3) & 1) << 3);
#pragma unroll
            for (int ma = 0; ma < 2; ++ma)
                ldsm4t(At[ma][0], At[ma][1], At[ma][2], At[ma][3],
                       kfb + (uint32_t)(arow * 264 + acol + ma * 16) * 2);
            int brow = r0 + (((lane >> 3) & 1) << 3) + (lane & 7);
            int bcol = head * 32 + ((lane >> 4) << 3);
#pragma unroll
            for (int nb = 0; nb < 2; ++nb)
                ldsm4t(Bt[nb][0], Bt[nb][1], Bt[nb][2], Bt[nb][3],
                       vfb + (uint32_t)(brow * 264 + bcol + nb * 16) * 2);
#pragma unroll
            for (int ma = 0; ma < 2; ++ma)
#pragma unroll
                for (int na = 0; na < 4; ++na)
                    mma16816h(acc[ma][na], At[ma],
                              Bt[na >> 1][(na & 1) * 2], Bt[na >> 1][(na & 1) * 2 + 1]);
        }
#pragma unroll
        for (int ma = 0; ma < 2; ++ma) {
            int d1 = ma * 16 + (lane >> 2), d2 = d1 + 8;
#pragma unroll
            for (int na = 0; na < 4; ++na) {
                int e = na * 8 + (lane & 3) * 2;
                *(uint32_t*)&g_KVp[tile][(head * 32 + d1) * 32 + e] =
                    pkh(acc[ma][na][0], acc[ma][na][1]);
                *(uint32_t*)&g_KVp[tile][(head * 32 + d2) * 32 + e] =
                    pkh(acc[ma][na][2], acc[ma][na][3]);
            }
        }
    }

    // ---- Ksum ----
    {
        float s = 0.0f;
#pragma unroll 8
        for (int r = 0; r < 64; ++r)
            s += __half2float(*(const __half*)(sm + S1_KF + (uint32_t)(r * 264 + t) * 2));
        g_Ksp[tile][t] = s;
    }
}

// ---------------- K2: Q-proj + Z + msg + out-proj (128-row, 2x4 warp grid) ----------------
__global__ __launch_bounds__(256, 1)
void k2_kernel(const float* __restrict__ q, const float* __restrict__ bq,
               float* __restrict__ out) {
    extern __shared__ unsigned char sm[];
    const uint32_t sb = smem_u32(sm);
    const int t = threadIdx.x, lane = t & 31, wid = t >> 5;
    const int wm = wid & 1, wn = wid >> 1;   // 2 m-halves x 4 n-quarters
    const int tile = blockIdx.x, row0 = tile * 128, b = tile >> 6;

    float* sZ  = (float*)(sm + J_Z);
    float* sKs = (float*)(sm + J_KS);
    float* sBq = (float*)(sm + J_BQ);
    const uint32_t aA = sb + J_A;

    // load BD + Ksum + bq
    {
        const uint4* src = (const uint4*)&g_BD[b][0][0][0];
        uint4* dst = (uint4*)(sm + J_BD);
#pragma unroll
        for (int i = 0; i < 5; ++i) dst[t + i * 256] = src[t + i * 256];
        if (t < 64) ((float4*)sKs)[t] = ((const float4*)(g_Ksum + b * 256))[t];
        else if (t < 128) ((float4*)sBq)[t - 64] = ((const float4*)bq)[t - 64];
    }

    // ---- Phase Qf: A = q tile; GEMM x Wq (both n-halves in regs); fmap in place ----
    build_A<128>(sm, t, row0, q);
    {
        float acc0[4][4][4], acc1[4][4][4];
#pragma unroll
        for (int ma = 0; ma < 4; ++ma)
#pragma unroll
            for (int na = 0; na < 4; ++na)
#pragma unroll
                for (int i = 0; i < 4; ++i) { acc0[ma][na][i] = 0.0f; acc1[ma][na][i] = 0.0f; }
        run_gemm2h(acc0, sb, aA, t, lane, wm * 64, wn * 32, 0, 0);
        run_gemm2h(acc1, sb, aA, t, lane, wm * 64, wn * 32, 0, 1);
        // trailing sync in run_gemm2h: all MMAs done; safe to overwrite A with Qf
#pragma unroll
        for (int nh = 0; nh < 2; ++nh) {
            float (*acc)[4][4] = nh ? acc1 : acc0;
#pragma unroll
            for (int ma = 0; ma < 4; ++ma) {
                int r1 = wm * 64 + ma * 16 + (lane >> 2);
                int r2 = r1 + 8;
#pragma unroll
                for (int na = 0; na < 4; ++na) {
                    int cg = nh * 128 + wn * 32 + na * 8 + (lane & 3) * 2;
                    *(uint32_t*)(sm + J_A + (uint32_t)(r1 * 264 + cg) * 2) =
                        pkh(fmap(acc[ma][na][0] + sBq[cg]), fmap(acc[ma][na][1] + sBq[cg + 1]));
                    *(uint32_t*)(sm + J_A + (uint32_t)(r2 * 264 + cg) * 2) =
                        pkh(fmap(acc[ma][na][2] + sBq[cg]), fmap(acc[ma][na][3] + sBq[cg + 1]));
                }
            }
        }
    }
    __syncthreads();

    // Z = 1/(Qf . Ksum + eps)   (128 rows x 8 heads = 1024 tasks)
#pragma unroll
    for (int i = 0; i < 4; ++i) {
        int task = t + i * 256;
        int r = task >> 3, h = task & 7;
        float dot = 0.0f;
#pragma unroll
        for (int dp = 0; dp < 16; ++dp) {
            int c = h * 32 + dp * 2;
            uint32_t w = *(const uint32_t*)(sm + J_A + (uint32_t)(r * 264 + c) * 2);
            __half2 hv; memcpy(&hv, &w, 4);
            dot += __half2float(hv.x) * sKs[c] + __half2float(hv.y) * sKs[c + 1];
        }
        sZ[r * 8 + h] = 1.0f / (dot + 1e-6f);
    }
    __syncthreads();

    // msg per head (round-12 shape): warp (wm, head=nh*4+wn), m64n32k32; Z-scale; overwrite A
    for (int nh = 0; nh < 2; ++nh) {
        int head = nh * 4 + wn;
        float acc[4][4][4];
#pragma unroll
        for (int ma = 0; ma < 4; ++ma)
#pragma unroll
            for (int na = 0; na < 4; ++na)
#pragma unroll
                for (int i = 0; i < 4; ++i) acc[ma][na][i] = 0.0f;
        uint32_t bdF = sb + J_BD + head * 2560;
        mma_block64s(acc, aA, wm * 64, head * 32,      bdF, 0, 0,  lane);
        mma_block64s(acc, aA, wm * 64, head * 32 + 16, bdF, 0, 16, lane);
        __syncwarp();
#pragma unroll
        for (int ma = 0; ma < 4; ++ma) {
            int r1 = wm * 64 + ma * 16 + (lane >> 2);
            int r2 = r1 + 8;
            float z1 = sZ[r1 * 8 + head], z2 = sZ[r2 * 8 + head];
#pragma unroll
            for (int na = 0; na < 4; ++na) {
                int cg = head * 32 + na * 8 + (lane & 3) * 2;
                *(uint32_t*)(sm + J_A + (uint32_t)(r1 * 264 + cg) * 2) =
                    pkh(acc[ma][na][0] * z1, acc[ma][na][1] * z1);
                *(uint32_t*)(sm + J_A + (uint32_t)(r2 * 264 + cg) * 2) =
                    pkh(acc[ma][na][2] * z2, acc[ma][na][3] * z2);
            }
        }
    }
    __syncthreads();

    // out = msg @ Wm^T: nh-halved staging, warp tile (wm*64, wn*32)
    for (int nh = 0; nh < 2; ++nh) {
        float acc[4][4][4];
#pragma unroll
        for (int ma = 0; ma < 4; ++ma)
#pragma unroll
            for (int na = 0; na < 4; ++na)
#pragma unroll
                for (int i = 0; i < 4; ++i) acc[ma][na][i] = 0.0f;
        run_gemm2h(acc, sb, aA, t, lane, wm * 64, wn * 32, 3, nh);
#pragma unroll
        for (int ma = 0; ma < 4; ++ma) {
            int r1 = wm * 64 + ma * 16 + (lane >> 2);
            int r2 = r1 + 8;
#pragma unroll
            for (int na = 0; na < 4; ++na) {
                int cg = nh * 128 + wn * 32 + na * 8 + (lane & 3) * 2;
                *(float2*)(out + (size_t)(row0 + r1) * 256 + cg) =
                    make_float2(acc[ma][na][0], acc[ma][na][1]);
                *(float2*)(out + (size_t)(row0 + r2) * 256 + cg) =
                    make_float2(acc[ma][na][2], acc[ma][na][3]);
            }
        }
    }
}

// ---------------------------------------------------------------------------
extern "C" void kernel_launch(void* const* d_in, const int* in_sizes, int n_in,
                              void* d_out, int out_size) {
    const float* q  = (const float*)d_in[0];
    const float* k  = (const float*)d_in[1];
    const float* v  = (const float*)d_in[2];
    const float* Wq = (const float*)d_in[3];
    const float* bq = (const float*)d_in[4];
    const float* Wk = (const float*)d_in[5];
    const float* bk = (const float*)d_in[6];
    const float* Wv = (const float*)d_in[7];
    const float* bv = (const float*)d_in[8];
    const float* Wm = (const float*)d_in[9];
    float* out = (float*)d_out;

    cudaFuncSetAttribute(k1_kernel, cudaFuncAttributeMaxDynamicSharedMemorySize, K1_SMEM);
    cudaFuncSetAttribute(k2_kernel, cudaFuncAttributeMaxDynamicSharedMemorySize, K2_SMEM);

    prep_w_kernel<<<128, 256>>>(Wq, Wk, Wv, Wm);
    k1_kernel<<<NT1, 256, K1_SMEM>>>(k, v, bk, bv);
    reduce_bd_kernel<<<256, 256>>>();
    k2_kernel<<<NT2, 256, K2_SMEM>>>(q, bq, out);
}